// round 4
// baseline (speedup 1.0000x reference)
#include <cuda_runtime.h>

// EMD / min-permutation matching on GB300.
//   B=32768, N=6, D=64.
//   cost[b] = (sum of all squared norms) - 2 * maxAssign(G),  G[n][m] = p_n . t_m
//   out[0] = sum_b cost[b]
//
// R4: 4 lanes/batch, 16 dims/lane, TWO half-passes (8 dims each) so each pass
// has 12 p-loads in flight up front + 12 streamed q-loads (R2's MLP profile)
// while keeping L=4's cheap 2-round butterfly and 8-wide DP.
// launch_bounds(128,5) -> <=102 regs -> 20 warps/SM.

#define BLOCK 128

__global__ __launch_bounds__(BLOCK, 5)
void emd_kernel(const float* __restrict__ preds,
                const float* __restrict__ targets,
                float* __restrict__ out, int B)
{
    const int g    = blockIdx.x * BLOCK + threadIdx.x;
    const int bRaw = g >> 2;          // batch index
    const int j    = g & 3;           // lane within 4-thread group
    const bool valid = (bRaw < B);
    const int b = valid ? bRaw : (B - 1);   // clamp keeps lanes converged

    const float* pp = preds   + (size_t)b * 384 + 4 * j;
    const float* tt = targets + (size_t)b * 384 + 4 * j;

    float G[36];
#pragma unroll
    for (int i = 0; i < 36; ++i) G[i] = 0.0f;
    float sq = 0.0f;

    // Two half-passes over D. Pass k covers dims {32k+4j..+3} and {32k+16+4j..+3}.
    // Within a 4-lane group each LDG.128 quartet covers a contiguous 64B segment.
#pragma unroll 1
    for (int k = 0; k < 2; ++k) {
        const float* pk = pp + k * 32;
        const float* tk = tt + k * 32;

        // 12 independent p-loads issued before any consumer
        float4 pa[6], pc[6];
#pragma unroll
        for (int n = 0; n < 6; ++n) {
            pa[n] = *(const float4*)(pk + n * 64);
            pc[n] = *(const float4*)(pk + n * 64 + 16);
        }

#pragma unroll
        for (int n = 0; n < 6; ++n) {
            sq += pa[n].x*pa[n].x + pa[n].y*pa[n].y + pa[n].z*pa[n].z + pa[n].w*pa[n].w;
            sq += pc[n].x*pc[n].x + pc[n].y*pc[n].y + pc[n].z*pc[n].z + pc[n].w*pc[n].w;
        }

        // Stream 6 target rows (2 loads each), accumulate Gram
#pragma unroll
        for (int m = 0; m < 6; ++m) {
            float4 qa = *(const float4*)(tk + m * 64);
            float4 qc = *(const float4*)(tk + m * 64 + 16);
            sq += qa.x*qa.x + qa.y*qa.y + qa.z*qa.z + qa.w*qa.w;
            sq += qc.x*qc.x + qc.y*qc.y + qc.z*qc.z + qc.w*qc.w;
#pragma unroll
            for (int n = 0; n < 6; ++n) {
                G[n * 6 + m] += pa[n].x*qa.x + pa[n].y*qa.y + pa[n].z*qa.z + pa[n].w*qa.w
                              + pc[n].x*qc.x + pc[n].y*qc.y + pc[n].z*qc.z + pc[n].w*qc.w;
            }
        }
    }

    // ---- 2-round butterfly over the 4-lane group (G + sq fully summed on all lanes)
#pragma unroll
    for (int o = 1; o < 4; o <<= 1) {
#pragma unroll
        for (int i = 0; i < 36; ++i)
            G[i] += __shfl_xor_sync(0xffffffffu, G[i], o);
        sq += __shfl_xor_sync(0xffffffffu, sq, o);
    }

    // ---- assignment DP (maximize), layered by popcount; 8 lanes/warp active
    float cost = 0.0f;
    if (j == 0 && valid) {
        float dp[64];
        dp[0] = 0.0f;
#pragma unroll
        for (int kk = 1; kk <= 6; ++kk) {
            const int r = kk - 1;
#pragma unroll
            for (int S = 1; S < 64; ++S) {
                if (__popc((unsigned)S) == kk) {
                    float best = -3.0e38f;
#pragma unroll
                    for (int m = 0; m < 6; ++m)
                        if (S & (1 << m))
                            best = fmaxf(best, dp[S ^ (1 << m)] + G[r * 6 + m]);
                    dp[S] = best;
                }
            }
        }
        cost = sq - 2.0f * dp[63];
    }

    // ---- warp + block reduction, one atomicAdd per block
#pragma unroll
    for (int o = 16; o > 0; o >>= 1)
        cost += __shfl_down_sync(0xffffffffu, cost, o);

    __shared__ float wsum[BLOCK / 32];
    if ((threadIdx.x & 31) == 0) wsum[threadIdx.x >> 5] = cost;
    __syncthreads();
    if (threadIdx.x == 0) {
        float s = 0.0f;
#pragma unroll
        for (int w = 0; w < BLOCK / 32; ++w) s += wsum[w];
        atomicAdd(out, s);
    }
}

extern "C" void kernel_launch(void* const* d_in, const int* in_sizes, int n_in,
                              void* d_out, int out_size)
{
    const float* preds   = (const float*)d_in[0];
    const float* targets = (const float*)d_in[1];
    const int B = in_sizes[0] / 384;   // 6 * 64 floats per batch

    cudaMemsetAsync(d_out, 0, sizeof(float));
    const long long threads = (long long)B * 4;
    const int grid = (int)((threads + BLOCK - 1) / BLOCK);
    emd_kernel<<<grid, BLOCK>>>(preds, targets, (float*)d_out, B);
}

// round 5
// speedup vs baseline: 1.1176x; 1.1176x over previous
#include <cuda_runtime.h>

// EMD / min-permutation matching on GB300.
//   B=32768, N=6, D=64.
//   cost[b] = (sum sq norms) - 2 * maxAssign(G),  G[n][m] = p_n . t_m
//   out[0] = sum_b cost[b]
//
// R5 = R2 (8 lanes/batch, lane j owns dims [4j,4j+4) U [32+4j,32+4j+4))
//      + cp.async staging of the 12 target loads so all 24 memory requests
//        per thread are in flight before any compute
//      + launch_bounds(128,5) for 20 warps/SM.
// SMEM stride 52 floats/thread -> LDS.128 conflict-free (52 % 32 == 20).

#define BLOCK   128
#define SSTRIDE 52

__device__ __forceinline__ void cp_async16(void* smem_dst, const void* gmem_src) {
    unsigned saddr = (unsigned)__cvta_generic_to_shared(smem_dst);
    asm volatile("cp.async.ca.shared.global [%0], [%1], 16;"
                 :: "r"(saddr), "l"(gmem_src) : "memory");
}

__global__ __launch_bounds__(BLOCK, 5)
void emd_kernel(const float* __restrict__ preds,
                const float* __restrict__ targets,
                float* __restrict__ out, int B)
{
    __shared__ float sh[BLOCK * SSTRIDE];   // 26624 B: q staging, 12 float4/thread

    const int t    = threadIdx.x;
    const int g    = blockIdx.x * BLOCK + t;
    const int bRaw = g >> 3;          // batch index
    const int j    = g & 7;           // lane within 8-thread group
    const bool valid = (bRaw < B);
    const int b = valid ? bRaw : (B - 1);   // clamp keeps lanes converged

    const float* pp = preds   + (size_t)b * 384 + 4 * j;
    const float* tt = targets + (size_t)b * 384 + 4 * j;
    float* myq = &sh[t * SSTRIDE];

    // ---- 1) fire all 12 target copies (async, land in smem)
#pragma unroll
    for (int m = 0; m < 6; ++m) {
        cp_async16(myq + 8 * m,     tt + m * 64);
        cp_async16(myq + 8 * m + 4, tt + m * 64 + 32);
    }
    asm volatile("cp.async.commit_group;" ::: "memory");

    // ---- 2) fire all 12 pred loads (register-resident)
    float4 pa[6], pc[6];
#pragma unroll
    for (int n = 0; n < 6; ++n) {
        pa[n] = *(const float4*)(pp + n * 64);
        pc[n] = *(const float4*)(pp + n * 64 + 32);
    }

    // ---- 3) compute on p while q is in flight
    float sq = 0.0f;
#pragma unroll
    for (int n = 0; n < 6; ++n) {
        sq += pa[n].x*pa[n].x + pa[n].y*pa[n].y + pa[n].z*pa[n].z + pa[n].w*pa[n].w;
        sq += pc[n].x*pc[n].x + pc[n].y*pc[n].y + pc[n].z*pc[n].z + pc[n].w*pc[n].w;
    }

    float G[36];
#pragma unroll
    for (int i = 0; i < 36; ++i) G[i] = 0.0f;

    // ---- 4) wait for own copies only (each thread reads its own slots)
    asm volatile("cp.async.wait_group 0;" ::: "memory");
    __syncwarp();

    // ---- 5) stream q from smem, accumulate Gram + sq
#pragma unroll
    for (int m = 0; m < 6; ++m) {
        float4 qa = *(const float4*)(myq + 8 * m);
        float4 qc = *(const float4*)(myq + 8 * m + 4);
        sq += qa.x*qa.x + qa.y*qa.y + qa.z*qa.z + qa.w*qa.w;
        sq += qc.x*qc.x + qc.y*qc.y + qc.z*qc.z + qc.w*qc.w;
#pragma unroll
        for (int n = 0; n < 6; ++n) {
            G[n * 6 + m] += pa[n].x*qa.x + pa[n].y*qa.y + pa[n].z*qa.z + pa[n].w*qa.w
                          + pc[n].x*qc.x + pc[n].y*qc.y + pc[n].z*qc.z + pc[n].w*qc.w;
        }
    }

    // ---- 6) butterfly reduce G and sq across the 8-lane group
#pragma unroll
    for (int o = 1; o < 8; o <<= 1) {
#pragma unroll
        for (int i = 0; i < 36; ++i)
            G[i] += __shfl_xor_sync(0xffffffffu, G[i], o);
        sq += __shfl_xor_sync(0xffffffffu, sq, o);
    }

    // ---- 7) assignment DP (maximize), layered by popcount; lane 0 of each group
    float cost = 0.0f;
    if (j == 0 && valid) {
        float dp[64];
        dp[0] = 0.0f;
#pragma unroll
        for (int k = 1; k <= 6; ++k) {
            const int r = k - 1;
#pragma unroll
            for (int S = 1; S < 64; ++S) {
                if (__popc((unsigned)S) == k) {
                    float best = -3.0e38f;
#pragma unroll
                    for (int m = 0; m < 6; ++m)
                        if (S & (1 << m))
                            best = fmaxf(best, dp[S ^ (1 << m)] + G[r * 6 + m]);
                    dp[S] = best;
                }
            }
        }
        cost = sq - 2.0f * dp[63];
    }

    // ---- 8) warp + block reduction, one atomicAdd per block
#pragma unroll
    for (int o = 16; o > 0; o >>= 1)
        cost += __shfl_down_sync(0xffffffffu, cost, o);

    __shared__ float wsum[BLOCK / 32];
    if ((t & 31) == 0) wsum[t >> 5] = cost;
    __syncthreads();
    if (t == 0) {
        float s = 0.0f;
#pragma unroll
        for (int w = 0; w < BLOCK / 32; ++w) s += wsum[w];
        atomicAdd(out, s);
    }
}

extern "C" void kernel_launch(void* const* d_in, const int* in_sizes, int n_in,
                              void* d_out, int out_size)
{
    const float* preds   = (const float*)d_in[0];
    const float* targets = (const float*)d_in[1];
    const int B = in_sizes[0] / 384;   // 6 * 64 floats per batch

    cudaMemsetAsync(d_out, 0, sizeof(float));
    const long long threads = (long long)B * 8;
    const int grid = (int)((threads + BLOCK - 1) / BLOCK);
    emd_kernel<<<grid, BLOCK>>>(preds, targets, (float*)d_out, B);
}

// round 6
// speedup vs baseline: 1.4981x; 1.3405x over previous
#include <cuda_runtime.h>

// EMD / min-permutation matching on GB300.
//   B=32768, N=6, D=64.
//   cost[b] = (sum sq norms) - 2 * maxAssign(G),  G[n][m] = p_n . t_m
//   out[0] = sum_b cost[b]
//
// R6 = R2's load/Gram phase (8 lanes/batch, direct LDG, streamed q)
//      + smem re-partition: partial G -> smem, one thread per batch sums the
//        8 partials and runs the subset DP with full lane utilization.
//      No shfl butterfly, no divergent DP.

#define BLOCK   128
#define SLOT    44    // floats per partial slot: 36 G + 1 sq + 7 pad
                      // 44 % 32 == 12 -> STS.128 conflict-free per 8-lane phase

__global__ __launch_bounds__(BLOCK, 5)
void emd_kernel(const float* __restrict__ preds,
                const float* __restrict__ targets,
                float* __restrict__ out, int B)
{
    __shared__ float sh[BLOCK * SLOT];    // 22528 B

    const int t    = threadIdx.x;
    const int g    = blockIdx.x * BLOCK + t;
    const int bRaw = g >> 3;          // batch index
    const int j    = g & 7;           // lane within 8-thread group
    const int b = (bRaw < B) ? bRaw : (B - 1);   // clamp keeps lanes converged

    const float* pp = preds   + (size_t)b * 384 + 4 * j;
    const float* tt = targets + (size_t)b * 384 + 4 * j;

    // ---- 1) 12 pred loads front-batched (register resident)
    float4 pa[6], pc[6];
#pragma unroll
    for (int n = 0; n < 6; ++n) {
        pa[n] = *(const float4*)(pp + n * 64);
        pc[n] = *(const float4*)(pp + n * 64 + 32);
    }

    float sq = 0.0f;
#pragma unroll
    for (int n = 0; n < 6; ++n) {
        sq += pa[n].x*pa[n].x + pa[n].y*pa[n].y + pa[n].z*pa[n].z + pa[n].w*pa[n].w;
        sq += pc[n].x*pc[n].x + pc[n].y*pc[n].y + pc[n].z*pc[n].z + pc[n].w*pc[n].w;
    }

    float G[36];
#pragma unroll
    for (int i = 0; i < 36; ++i) G[i] = 0.0f;

    // ---- 2) stream target rows, accumulate partial Gram + sq
#pragma unroll
    for (int m = 0; m < 6; ++m) {
        float4 qa = *(const float4*)(tt + m * 64);
        float4 qc = *(const float4*)(tt + m * 64 + 32);
        sq += qa.x*qa.x + qa.y*qa.y + qa.z*qa.z + qa.w*qa.w;
        sq += qc.x*qc.x + qc.y*qc.y + qc.z*qc.z + qc.w*qc.w;
#pragma unroll
        for (int n = 0; n < 6; ++n) {
            G[n * 6 + m] += pa[n].x*qa.x + pa[n].y*qa.y + pa[n].z*qa.z + pa[n].w*qa.w
                          + pc[n].x*qc.x + pc[n].y*qc.y + pc[n].z*qc.z + pc[n].w*qc.w;
        }
    }

    // ---- 3) write partial (G, sq) to own slot; STS.128, conflict-free
    {
        float* slot = &sh[t * SLOT];
#pragma unroll
        for (int i = 0; i < 9; ++i)
            *(float4*)&slot[4 * i] = make_float4(G[4*i], G[4*i+1], G[4*i+2], G[4*i+3]);
        slot[36] = sq;
    }
    __syncthreads();

    // ---- 4) one thread per batch: sum 8 partials, run DP
    float cost = 0.0f;
    if (t < BLOCK / 8) {                         // 16 batches per CTA
        const int bOut = blockIdx.x * (BLOCK / 8) + t;
        float A[37];
#pragma unroll
        for (int i = 0; i < 37; ++i) A[i] = 0.0f;

#pragma unroll
        for (int l = 0; l < 8; ++l) {
            const int rot = (l + t) & 7;                 // de-conflict rotation
            const float* slot = &sh[(t * 8 + rot) * SLOT];
#pragma unroll
            for (int e = 0; e < 9; ++e) {
                float4 v = *(const float4*)&slot[4 * e];
                A[4*e]   += v.x;  A[4*e+1] += v.y;
                A[4*e+2] += v.z;  A[4*e+3] += v.w;
            }
            A[36] += slot[36];
        }

        if (bOut < B) {
            float dp[64];
            dp[0] = 0.0f;
#pragma unroll
            for (int k = 1; k <= 6; ++k) {
                const int r = k - 1;
#pragma unroll
                for (int S = 1; S < 64; ++S) {
                    if (__popc((unsigned)S) == k) {
                        float best = -3.0e38f;
#pragma unroll
                        for (int m = 0; m < 6; ++m)
                            if (S & (1 << m))
                                best = fmaxf(best, dp[S ^ (1 << m)] + A[r * 6 + m]);
                        dp[S] = best;
                    }
                }
            }
            cost = A[36] - 2.0f * dp[63];
        }
    }

    // ---- 5) reduce the 16 costs (first half-warp) and atomicAdd once
    if (t < 32) {
#pragma unroll
        for (int o = 8; o > 0; o >>= 1)
            cost += __shfl_down_sync(0xffffffffu, cost, o);
        if (t == 0) atomicAdd(out, cost);
    }
}

extern "C" void kernel_launch(void* const* d_in, const int* in_sizes, int n_in,
                              void* d_out, int out_size)
{
    const float* preds   = (const float*)d_in[0];
    const float* targets = (const float*)d_in[1];
    const int B = in_sizes[0] / 384;   // 6 * 64 floats per batch

    cudaMemsetAsync(d_out, 0, sizeof(float));
    const long long threads = (long long)B * 8;
    const int grid = (int)((threads + BLOCK - 1) / BLOCK);
    emd_kernel<<<grid, BLOCK>>>(preds, targets, (float*)d_out, B);
}